// round 9
// baseline (speedup 1.0000x reference)
#include <cuda_runtime.h>

// FeatureSim: attn[b,i,j] = softmax_j( sum_k w[k]*|x[b,i,k]-x[b,j,k]| ), mask j < len[b].
// B=8, L=1024, F=16 (first 11 used), out f32 [8,1024,1024].
//
// R9: kill the e-slab + fix wave quantization.
//     - BQ=4, grid 2048: 5 half-size waves instead of 3 (last wave 31% full) -> ~17%.
//     - e[4][4] stays in REGISTERS end-to-end: no STS / reduce-LDS / normalize-LDS.
//       Row sums: 3 FADD + 5-SHFL butterfly per row (4 independent chains after the
//       compute loop), red[4][8] smem exchange, warp fold, broadcast inv.
//     - mask applied as post-ex2 select (saves 4 bias GPRs; alu pipe is at 4%).
//     - kept from R8: pure FADD/FFMA core with free |.|/- source modifiers,
//       ex2.approx, C=4 cols/thread, TPB=256, 3 blocks/SM pinned.

#define L_SEQ 1024
#define FDIM  16
#define NF    11
#define BQ    4             // rows per block
#define TPB   256           // each thread owns 4 consecutive key columns
#define BPB   (L_SEQ / BQ)  // 256 blocks per batch

__device__ __forceinline__ float ex2(float a) {
    float r; asm("ex2.approx.f32 %0, %1;" : "=f"(r) : "f"(a)); return r;
}

#define LOG2E 1.4426950408889634f

__global__ __launch_bounds__(TPB, 3)
void featsim_kernel(const float* __restrict__ x,
                    const int*   __restrict__ lens,
                    const float* __restrict__ w,
                    float*       __restrict__ out)
{
    const int b    = blockIdx.x / BPB;
    const int rb   = blockIdx.x % BPB;
    const int i0   = rb * BQ;
    const int tid  = threadIdx.x;
    const int lane = tid & 31;
    const int warp = tid >> 5;          // 0..7
    const int j0   = tid * 4;

    __shared__ __align__(16) float sq[BQ][12];   // raw queries (11 used, pad 0)
    __shared__ float red[BQ][8];                 // per-warp row partials
    __shared__ float inv_s[BQ];                  // per-row 1/sum

    // Signed per-feature scale wl_k = w_k * log2e.
    float wl[NF];
#pragma unroll
    for (int k = 0; k < NF; ++k) wl[k] = w[k] * LOG2E;

    // Stage raw queries.
    if (tid < BQ * 12) {
        int r = tid / 12, k = tid - r * 12;
        sq[r][k] = (k < NF) ? x[(size_t)(b * L_SEQ + i0 + r) * FDIM + k] : 0.f;
    }

    // Keys: 4 cols, raw floats from LDG (L2-resident).
    float kk[4][NF];
#pragma unroll
    for (int cc = 0; cc < 4; ++cc) {
        const float4* kp = reinterpret_cast<const float4*>(
            x + (size_t)(b * L_SEQ + j0 + cc) * FDIM);
        float4 a = kp[0], c = kp[1], d = kp[2];
        kk[cc][0] = a.x;  kk[cc][1] = a.y;  kk[cc][2]  = a.z;  kk[cc][3] = a.w;
        kk[cc][4] = c.x;  kk[cc][5] = c.y;  kk[cc][6]  = c.z;  kk[cc][7] = c.w;
        kk[cc][8] = d.x;  kk[cc][9] = d.y;  kk[cc][10] = d.z;
    }

    const int len = lens[b];
    const bool v0 = (j0 + 0) < len, v1 = (j0 + 1) < len,
               v2 = (j0 + 2) < len, v3 = (j0 + 3) < len;

    __syncthreads();

    // ---- compute all BQ rows; e stays in registers ----
    float e[BQ][4];
#pragma unroll
    for (int r = 0; r < BQ; ++r) {
        const float4* qp = reinterpret_cast<const float4*>(sq[r]);
        float s0 = 0.f, s1 = 0.f, s2 = 0.f, s3 = 0.f;
        {
            float4 qa = qp[0];                      // features 0..3
#pragma unroll
            for (int k = 0; k < 4; ++k) {
                const float q = (&qa.x)[k], wk = wl[k];
                s0 = fmaf(fabsf(q - kk[0][k]), wk, s0);
                s1 = fmaf(fabsf(q - kk[1][k]), wk, s1);
                s2 = fmaf(fabsf(q - kk[2][k]), wk, s2);
                s3 = fmaf(fabsf(q - kk[3][k]), wk, s3);
            }
        }
        {
            float4 qb = qp[1];                      // features 4..7
#pragma unroll
            for (int k = 0; k < 4; ++k) {
                const float q = (&qb.x)[k], wk = wl[k + 4];
                s0 = fmaf(fabsf(q - kk[0][k + 4]), wk, s0);
                s1 = fmaf(fabsf(q - kk[1][k + 4]), wk, s1);
                s2 = fmaf(fabsf(q - kk[2][k + 4]), wk, s2);
                s3 = fmaf(fabsf(q - kk[3][k + 4]), wk, s3);
            }
        }
        {
            float4 qc = qp[2];                      // features 8..10
#pragma unroll
            for (int k = 0; k < 3; ++k) {
                const float q = (&qc.x)[k], wk = wl[k + 8];
                s0 = fmaf(fabsf(q - kk[0][k + 8]), wk, s0);
                s1 = fmaf(fabsf(q - kk[1][k + 8]), wk, s1);
                s2 = fmaf(fabsf(q - kk[2][k + 8]), wk, s2);
                s3 = fmaf(fabsf(q - kk[3][k + 8]), wk, s3);
            }
        }
        e[r][0] = v0 ? ex2(s0) : 0.f;
        e[r][1] = v1 ? ex2(s1) : 0.f;
        e[r][2] = v2 ? ex2(s2) : 0.f;
        e[r][3] = v3 ? ex2(s3) : 0.f;
    }

    // ---- row sums: 4 independent butterfly chains ----
    float ps[BQ];
#pragma unroll
    for (int r = 0; r < BQ; ++r)
        ps[r] = (e[r][0] + e[r][1]) + (e[r][2] + e[r][3]);
#pragma unroll
    for (int o = 16; o > 0; o >>= 1) {
#pragma unroll
        for (int r = 0; r < BQ; ++r)
            ps[r] += __shfl_xor_sync(0xffffffffu, ps[r], o);
    }
    if (lane < BQ) red[lane][warp] = ps[lane];   // lane r stores row r's warp sum
    __syncthreads();

    // ---- fold 8 warp partials per row (warps 0..3, one row each) ----
    if (warp < BQ) {
        float v = (lane < 8) ? red[warp][lane] : 0.f;
#pragma unroll
        for (int o = 4; o > 0; o >>= 1)
            v += __shfl_xor_sync(0xffffffffu, v, o);
        if (lane == 0) {
            float inv; asm("rcp.approx.f32 %0, %1;" : "=f"(inv) : "f"(v));
            inv_s[warp] = inv;                   // len>=1 => v>0
        }
    }
    __syncthreads();

    // ---- normalize from registers + store ----
    float4* outb = reinterpret_cast<float4*>(out) + (size_t)(b * L_SEQ + i0) * (L_SEQ / 4);
#pragma unroll
    for (int r = 0; r < BQ; ++r) {
        float inv = inv_s[r];
        outb[(size_t)r * (L_SEQ / 4) + tid] =
            make_float4(e[r][0] * inv, e[r][1] * inv, e[r][2] * inv, e[r][3] * inv);
    }
}

extern "C" void kernel_launch(void* const* d_in, const int* in_sizes, int n_in,
                              void* d_out, int out_size)
{
    const float* x    = (const float*)d_in[0];   // [8,1024,16] f32
    const int*   lens = (const int*)d_in[1];     // [8] i32
    const float* w    = (const float*)d_in[2];   // [11] f32
    float*       out  = (float*)d_out;           // [8,1024,1024] f32

    dim3 grid(8 * BPB);   // 2048 blocks
    dim3 block(TPB);
    featsim_kernel<<<grid, block>>>(x, lens, w, out);
}

// round 10
// speedup vs baseline: 1.4766x; 1.4766x over previous
#include <cuda_runtime.h>

// FeatureSim: attn[b,i,j] = softmax_j( sum_k w[k]*|x[b,i,k]-x[b,j,k]| ), mask j < len[b].
// B=8, L=1024, F=16 (first 11 used), out f32 [8,1024,1024].
//
// R10: R8 (best, 27.0us) + fused reduce/normalize epilogue.
//      - compute phase unchanged: pure FADD/FFMA core (free |.| and - source
//        modifiers), ex2.approx, C=4 cols/thread, BQ=8, TPB=256, 3 blocks/SM,
//        e staged once to the smem slab.
//      - epilogue: ONE pass. Warp w owns row w: loads the row's 32 float4 slices
//        (v[8] in regs), sums -> butterfly -> inv, then scales the SAME registers
//        and stores straight to gmem. Kills the separate normalize re-read
//        (8 LDS.128/thread), the red[]/inv exchange, and one barrier.
//      - 2 barriers total; ~20% less L1 traffic than R8.

#define L_SEQ 1024
#define FDIM  16
#define NF    11
#define BQ    8             // rows per block == warps per block
#define TPB   256           // each thread owns 4 consecutive key columns
#define BPB   (L_SEQ / BQ)  // 128 blocks per batch

__device__ __forceinline__ float ex2(float a) {
    float r; asm("ex2.approx.f32 %0, %1;" : "=f"(r) : "f"(a)); return r;
}

#define LOG2E 1.4426950408889634f

__global__ __launch_bounds__(TPB, 3)
void featsim_kernel(const float* __restrict__ x,
                    const int*   __restrict__ lens,
                    const float* __restrict__ w,
                    float*       __restrict__ out)
{
    const int b    = blockIdx.x / BPB;
    const int rb   = blockIdx.x % BPB;
    const int i0   = rb * BQ;
    const int tid  = threadIdx.x;
    const int lane = tid & 31;
    const int warp = tid >> 5;          // 0..7, warp w owns row w in the epilogue
    const int j0   = tid * 4;

    __shared__ __align__(16) float sq[BQ][12];      // raw queries (11 used, pad 0)
    __shared__ __align__(16) float se[BQ][L_SEQ];   // unnormalized e staging (32 KB)

    // Signed per-feature scale wl_k = w_k * log2e (sign rides the FFMA multiplier;
    // |d| comes from the free abs source modifier).
    float wl[NF];
#pragma unroll
    for (int k = 0; k < NF; ++k) wl[k] = w[k] * LOG2E;

    // Stage raw queries.
    if (tid < BQ * 12) {
        int r = tid / 12, k = tid - r * 12;
        sq[r][k] = (k < NF) ? x[(size_t)(b * L_SEQ + i0 + r) * FDIM + k] : 0.f;
    }

    // Keys: 4 cols, raw floats straight from LDG (L2-resident).
    float kk[4][NF];
#pragma unroll
    for (int cc = 0; cc < 4; ++cc) {
        const float4* kp = reinterpret_cast<const float4*>(
            x + (size_t)(b * L_SEQ + j0 + cc) * FDIM);
        float4 a = kp[0], c = kp[1], d = kp[2];
        kk[cc][0] = a.x;  kk[cc][1] = a.y;  kk[cc][2]  = a.z;  kk[cc][3] = a.w;
        kk[cc][4] = c.x;  kk[cc][5] = c.y;  kk[cc][6]  = c.z;  kk[cc][7] = c.w;
        kk[cc][8] = d.x;  kk[cc][9] = d.y;  kk[cc][10] = d.z;
    }

    // Key-mask as accumulator bias: invalid col -> -1e30 -> ex2 -> exact 0.
    const int len = lens[b];
    float bias[4];
#pragma unroll
    for (int cc = 0; cc < 4; ++cc) bias[cc] = (j0 + cc < len) ? 0.f : -1e30f;

    __syncthreads();

    // ---- compute: 3 LDS.128 per row + 88 FADD/FFMA (one pipe, free |.| and -) ----
#pragma unroll
    for (int r = 0; r < BQ; ++r) {
        const float4* qp = reinterpret_cast<const float4*>(sq[r]);
        float4 qa = qp[0];              // features 0..3
        float4 qb = qp[1];              // features 4..7
        float4 qc = qp[2];              // features 8..10 (+pad)
        const float qs[NF] = { qa.x, qa.y, qa.z, qa.w,
                               qb.x, qb.y, qb.z, qb.w,
                               qc.x, qc.y, qc.z };

        float s0 = bias[0], s1 = bias[1], s2 = bias[2], s3 = bias[3];
#pragma unroll
        for (int k = 0; k < NF; ++k) {
            const float q = qs[k], wk = wl[k];
            s0 = fmaf(fabsf(q - kk[0][k]), wk, s0);
            s1 = fmaf(fabsf(q - kk[1][k]), wk, s1);
            s2 = fmaf(fabsf(q - kk[2][k]), wk, s2);
            s3 = fmaf(fabsf(q - kk[3][k]), wk, s3);
        }

        *reinterpret_cast<float4*>(&se[r][j0]) =
            make_float4(ex2(s0), ex2(s1), ex2(s2), ex2(s3));
    }
    __syncthreads();

    // ---- fused reduce + normalize + store: warp w owns row w ----
    {
        float4 v[8];
        float acc = 0.f;
#pragma unroll
        for (int p = 0; p < 8; ++p) {
            v[p] = *reinterpret_cast<float4*>(&se[warp][lane * 4 + p * 128]);
            acc += (v[p].x + v[p].y) + (v[p].z + v[p].w);
        }
#pragma unroll
        for (int o = 16; o > 0; o >>= 1)
            acc += __shfl_xor_sync(0xffffffffu, acc, o);

        float inv; asm("rcp.approx.f32 %0, %1;" : "=f"(inv) : "f"(acc));  // len>=1 => acc>0

        float4* orow = reinterpret_cast<float4*>(
            out + (size_t)(b * L_SEQ + i0 + warp) * L_SEQ);
#pragma unroll
        for (int p = 0; p < 8; ++p) {
            orow[p * 32 + lane] =
                make_float4(v[p].x * inv, v[p].y * inv, v[p].z * inv, v[p].w * inv);
        }
    }
}

extern "C" void kernel_launch(void* const* d_in, const int* in_sizes, int n_in,
                              void* d_out, int out_size)
{
    const float* x    = (const float*)d_in[0];   // [8,1024,16] f32
    const int*   lens = (const int*)d_in[1];     // [8] i32
    const float* w    = (const float*)d_in[2];   // [11] f32
    float*       out  = (float*)d_out;           // [8,1024,1024] f32

    dim3 grid(8 * BPB);   // 1024 blocks
    dim3 block(TPB);
    featsim_kernel<<<grid, block>>>(x, lens, w, out);
}